// round 15
// baseline (speedup 1.0000x reference)
#include <cuda_runtime.h>
#include <cuda_bf16.h>
#include <cstdint>

// Fixed problem shapes
#define BV 4
#define DV 48
#define HV 32
#define WV 88
#define CV 64
#define NXV 200
#define NYV 200
#define HWV (HV * WV)
#define NPRIME (BV * DV * HV * WV)       // 540672 points (divisible by 32)
#define NXY (NXV * NYV)                  // 40000
#define SCRATCH_ELEMS (BV * NXY * CV)    // 10,240,000 floats = 40.96 MB
#define TSZ 64                           // transpose tile: 64 nxy x 64 ch
#define NTILE (NXY / TSZ)                // 625 tiles per batch

// Point-row scratch: [b][nxy][64ch]; a voxel's 64-channel row is one
// contiguous 256B region. Zero at module load; bev_unpack_kernel re-zeroes
// each tile right after consuming it, so the invariant holds for the
// correctness run and every graph replay.
__device__ __align__(256) float g_scratch[SCRATCH_ELEMS];

__global__ void __launch_bounds__(256, 5)
bev_scatter_kernel(const float* __restrict__ x,
                   const float* __restrict__ geom,
                   const float* __restrict__ mask,
                   const float* __restrict__ dxp,
                   const float* __restrict__ bxp) {
    const int lane = threadIdx.x & 31;
    const int warp = (blockIdx.x * blockDim.x + threadIdx.x) >> 5;
    const int nw   = (gridDim.x * blockDim.x) >> 5;

    const float dx0 = dxp[0], dx1 = dxp[1], dx2 = dxp[2];
    const float b0 = bxp[0] - 0.5f * dx0;
    const float b1 = bxp[1] - 0.5f * dx1;
    const float b2 = bxp[2] - 0.5f * dx2;

    const int half = lane >> 4;          // which of the 2 points per iteration
    const int sl   = lane & 15;          // 4-channel group within the point

    // Accumulator lines are evict-last: they win L2 arbitration against the
    // evict-first streaming reads.
    uint64_t pol;
    asm("createpolicy.fractional.L2::evict_last.b64 %0, 1.0;" : "=l"(pol));

    for (int p0 = warp * 32; p0 < NPRIME; p0 += nw * 32) {
        // ---- phase 1: all 32 lanes compute one point's voxel id each ----
        const int p = p0 + lane;
        // Streaming reads; fp32 div + truncation matches reference astype(int32)
        const float gx = (__ldcs(geom + p * 3 + 0) - b0) / dx0;
        const float gy = (__ldcs(geom + p * 3 + 1) - b1) / dx1;
        const float gz = (__ldcs(geom + p * 3 + 2) - b2) / dx2;
        const int ix = (int)gx;
        const int iy = (int)gy;
        const int iz = (int)gz;

        const int hw = p % HWV;
        const int bn = p / (DV * HWV);   // batch index (N=1)

        int vox = -1;
        if ((ix >= 0) & (ix < NXV) &
            (iy >= 0) & (iy < NYV) &
            (iz >= 0) & (iz < 1) &
            (__ldcs(mask + (bn * 2 + 1) * HWV + hw) > 0.5f)) {
            vox = bn * NXY + ix * NYV + iy;
        }

        // ---- phase 2: 4 batches x (4 streaming loads, then 4 REDs) ----
        #pragma unroll
        for (int bt = 0; bt < 4; bt++) {
            int    vj[4];
            float4 v[4];
            #pragma unroll
            for (int j = 0; j < 4; j++) {
                const int idx = bt * 8 + 2 * j + half;
                vj[j] = __shfl_sync(0xffffffffu, vox, idx);
                if (vj[j] >= 0) {
                    v[j] = __ldcs(reinterpret_cast<const float4*>(
                        x + (size_t)(p0 + idx) * CV + 4 * sl));
                }
            }
            #pragma unroll
            for (int j = 0; j < 4; j++) {
                if (vj[j] >= 0) {
                    // 16 lanes -> one contiguous 256B region; evict-last RMW
                    float* dst = g_scratch + (size_t)vj[j] * CV + 4 * sl;
                    asm volatile(
                        "red.global.L2::cache_hint.add.v4.f32 "
                        "[%0], {%1, %2, %3, %4}, %5;"
                        :: "l"(dst), "f"(v[j].x), "f"(v[j].y),
                           "f"(v[j].z), "f"(v[j].w), "l"(pol)
                        : "memory");
                }
            }
        }
    }
}

// Fused: [b][nxy][64] -> [b][64][nxy] transpose AND scratch re-zero.
// Each block reads its 16KB tile into smem, stores zeros back to the SAME
// addresses it just read (same thread, same idx set -> no race, lines L2-hot),
// then writes the transposed tile to out with streaming float4 stores.
__global__ void __launch_bounds__(256)
bev_unpack_kernel(float* __restrict__ out) {
    const int tile = blockIdx.x % NTILE;
    const int b    = blockIdx.x / NTILE;
    const int nxy0 = tile * TSZ;
    const int t    = threadIdx.x;

    __shared__ float sm[TSZ][CV + 4];    // pad 4: float4-aligned, skews banks

    float4* src = reinterpret_cast<float4*>(
        g_scratch + ((size_t)b * NXY + nxy0) * CV);
    const float4 z = make_float4(0.f, 0.f, 0.f, 0.f);
    #pragma unroll
    for (int k = 0; k < 4; k++) {
        const int idx = t + k * 256;     // 0..1023
        const int r   = idx >> 4;        // nxy row in tile
        const int c4  = idx & 15;        // float4 column
        const float4 v = src[idx];
        *reinterpret_cast<float4*>(&sm[r][4 * c4]) = v;
        src[idx] = z;                    // re-zero: same address, L2-hot
    }
    __syncthreads();

    const int c = t >> 2;
    const int q = t & 3;
    #pragma unroll
    for (int k = 0; k < 4; k++) {
        const int r0 = 16 * q + 4 * k;   // covers 16 nxy per thread
        float4 o4;
        o4.x = sm[r0 + 0][c];
        o4.y = sm[r0 + 1][c];
        o4.z = sm[r0 + 2][c];
        o4.w = sm[r0 + 3][c];
        __stcs(reinterpret_cast<float4*>(
            out + ((size_t)(b * CV + c)) * NXY + nxy0 + r0), o4);
    }
}

extern "C" void kernel_launch(void* const* d_in, const int* in_sizes, int n_in,
                              void* d_out, int out_size) {
    const float* x    = (const float*)d_in[0];
    const float* geom = (const float*)d_in[1];
    const float* mask = (const float*)d_in[2];
    const float* dx   = (const float*)d_in[3];
    const float* bx   = (const float*)d_in[4];
    float* out = (float*)d_out;

    // 1) masked scatter; evict-last REDs pin the accumulator in L2.
    //    740 = 148 SMs x 5 blocks: exactly one persistent wave.
    bev_scatter_kernel<<<740, 256>>>(x, geom, mask, dx, bx);

    // 2) fused transpose + scratch re-zero + streaming out-writes
    bev_unpack_kernel<<<BV * NTILE, 256>>>(out);
}

// round 16
// speedup vs baseline: 1.1179x; 1.1179x over previous
#include <cuda_runtime.h>
#include <cuda_bf16.h>
#include <cstdint>

// Fixed problem shapes
#define BV 4
#define DV 48
#define HV 32
#define WV 88
#define CV 64
#define NXV 200
#define NYV 200
#define HWV (HV * WV)
#define NPRIME (BV * DV * HV * WV)       // 540672 points (divisible by 32)
#define NXY (NXV * NYV)                  // 40000
#define SCRATCH_ELEMS (BV * NXY * CV)    // 10,240,000 floats = 40.96 MB
#define TSZ 64                           // transpose tile: 64 nxy x 64 ch
#define NTILE (NXY / TSZ)                // 625 tiles per batch

// TMA-bulk rezero params
#define CHUNK_BYTES 32768                // 32KB per bulk store
#define NCHUNK ((SCRATCH_ELEMS * 4) / CHUNK_BYTES)   // 1250 exactly

// Point-row scratch: [b][nxy][64ch]; a voxel's 64-channel row is one
// contiguous 256B region. Zero at module load; rezero_kernel restores the
// invariant at the END of every call (valid across graph replays) and leaves
// the lines dirty-resident in L2 for the next scatter.
__device__ __align__(256) float g_scratch[SCRATCH_ELEMS];

__global__ void __launch_bounds__(256, 5)
bev_scatter_kernel(const float* __restrict__ x,
                   const float* __restrict__ geom,
                   const float* __restrict__ mask,
                   const float* __restrict__ dxp,
                   const float* __restrict__ bxp) {
    const int lane = threadIdx.x & 31;
    const int warp = (blockIdx.x * blockDim.x + threadIdx.x) >> 5;
    const int nw   = (gridDim.x * blockDim.x) >> 5;

    const float dx0 = dxp[0], dx1 = dxp[1], dx2 = dxp[2];
    const float b0 = bxp[0] - 0.5f * dx0;
    const float b1 = bxp[1] - 0.5f * dx1;
    const float b2 = bxp[2] - 0.5f * dx2;

    const int half = lane >> 4;          // which of the 2 points per iteration
    const int sl   = lane & 15;          // 4-channel group within the point

    // Accumulator lines are evict-last: they win L2 arbitration against the
    // evict-first streaming reads.
    uint64_t pol;
    asm("createpolicy.fractional.L2::evict_last.b64 %0, 1.0;" : "=l"(pol));

    for (int p0 = warp * 32; p0 < NPRIME; p0 += nw * 32) {
        // ---- phase 1: all 32 lanes compute one point's voxel id each ----
        const int p = p0 + lane;
        // Streaming reads; fp32 div + truncation matches reference astype(int32)
        const float gx = (__ldcs(geom + p * 3 + 0) - b0) / dx0;
        const float gy = (__ldcs(geom + p * 3 + 1) - b1) / dx1;
        const float gz = (__ldcs(geom + p * 3 + 2) - b2) / dx2;
        const int ix = (int)gx;
        const int iy = (int)gy;
        const int iz = (int)gz;

        const int hw = p % HWV;
        const int bn = p / (DV * HWV);   // batch index (N=1)

        int vox = -1;
        if ((ix >= 0) & (ix < NXV) &
            (iy >= 0) & (iy < NYV) &
            (iz >= 0) & (iz < 1) &
            (__ldcs(mask + (bn * 2 + 1) * HWV + hw) > 0.5f)) {
            vox = bn * NXY + ix * NYV + iy;
        }

        // ---- phase 2: 4 batches x (4 streaming loads, then 4 REDs) ----
        #pragma unroll
        for (int bt = 0; bt < 4; bt++) {
            int    vj[4];
            float4 v[4];
            #pragma unroll
            for (int j = 0; j < 4; j++) {
                const int idx = bt * 8 + 2 * j + half;
                vj[j] = __shfl_sync(0xffffffffu, vox, idx);
                if (vj[j] >= 0) {
                    v[j] = __ldcs(reinterpret_cast<const float4*>(
                        x + (size_t)(p0 + idx) * CV + 4 * sl));
                }
            }
            #pragma unroll
            for (int j = 0; j < 4; j++) {
                if (vj[j] >= 0) {
                    // 16 lanes -> one contiguous 256B region; evict-last RMW
                    float* dst = g_scratch + (size_t)vj[j] * CV + 4 * sl;
                    asm volatile(
                        "red.global.L2::cache_hint.add.v4.f32 "
                        "[%0], {%1, %2, %3, %4}, %5;"
                        :: "l"(dst), "f"(v[j].x), "f"(v[j].y),
                           "f"(v[j].z), "f"(v[j].w), "l"(pol)
                        : "memory");
                }
            }
        }
    }
}

// [b][nxy][64] -> [b][64][nxy] transpose through a 64x64 smem tile.
// Scratch is read-only here (re-zero is a separate TMA kernel -- R3/R15
// proved same-kernel read-then-zero is pathological). Out writes stream.
__global__ void __launch_bounds__(256)
bev_unpack_kernel(float* __restrict__ out) {
    const int tile = blockIdx.x % NTILE;
    const int b    = blockIdx.x / NTILE;
    const int nxy0 = tile * TSZ;
    const int t    = threadIdx.x;

    __shared__ float sm[TSZ][CV + 4];    // pad 4: float4-aligned, skews banks

    const float4* src = reinterpret_cast<const float4*>(
        g_scratch + ((size_t)b * NXY + nxy0) * CV);
    #pragma unroll
    for (int k = 0; k < 4; k++) {
        const int idx = t + k * 256;     // 0..1023
        const int r   = idx >> 4;        // nxy row in tile
        const int c4  = idx & 15;        // float4 column
        *reinterpret_cast<float4*>(&sm[r][4 * c4]) = src[idx];
    }
    __syncthreads();

    const int c = t >> 2;
    const int q = t & 3;
    #pragma unroll
    for (int k = 0; k < 4; k++) {
        const int r0 = 16 * q + 4 * k;   // covers 16 nxy per thread
        float4 o4;
        o4.x = sm[r0 + 0][c];
        o4.y = sm[r0 + 1][c];
        o4.z = sm[r0 + 2][c];
        o4.w = sm[r0 + 3][c];
        __stcs(reinterpret_cast<float4*>(
            out + ((size_t)(b * CV + c)) * NXY + nxy0 + r0), o4);
    }
}

// Re-zero via TMA bulk stores: each block zeroes a 32KB smem buffer once and
// fires ONE cp.async.bulk store for its chunk -- the 40MB fill runs on the
// TMA engine instead of 2.5M STG wavefronts through the SM issue path.
__global__ void __launch_bounds__(256)
rezero_kernel() {
    __shared__ __align__(128) float zbuf[CHUNK_BYTES / 4];
    const int t = threadIdx.x;
    float4* zb = reinterpret_cast<float4*>(zbuf);
    #pragma unroll
    for (int k = 0; k < CHUNK_BYTES / 16 / 256; k++) {
        zb[t + k * 256] = make_float4(0.f, 0.f, 0.f, 0.f);
    }
    __syncthreads();
    asm volatile("fence.proxy.async.shared::cta;" ::: "memory");

    if (t == 0) {
        char* dst = reinterpret_cast<char*>(g_scratch)
                    + (size_t)blockIdx.x * CHUNK_BYTES;
        uint32_t saddr;
        asm("{ .reg .u64 tmp; cvta.to.shared.u64 tmp, %1; cvt.u32.u64 %0, tmp; }"
            : "=r"(saddr) : "l"(zbuf));
        asm volatile(
            "cp.async.bulk.global.shared::cta.bulk_group [%0], [%1], %2;"
            :: "l"(dst), "r"(saddr), "r"((uint32_t)CHUNK_BYTES)
            : "memory");
        asm volatile("cp.async.bulk.commit_group;" ::: "memory");
        asm volatile("cp.async.bulk.wait_group 0;" ::: "memory");
    }
}

extern "C" void kernel_launch(void* const* d_in, const int* in_sizes, int n_in,
                              void* d_out, int out_size) {
    const float* x    = (const float*)d_in[0];
    const float* geom = (const float*)d_in[1];
    const float* mask = (const float*)d_in[2];
    const float* dx   = (const float*)d_in[3];
    const float* bx   = (const float*)d_in[4];
    float* out = (float*)d_out;

    // 1) masked scatter; evict-last REDs pin the accumulator in L2.
    //    740 = 148 SMs x 5 blocks: exactly one persistent wave.
    bev_scatter_kernel<<<740, 256>>>(x, geom, mask, dx, bx);

    // 2) [nxy][64] -> [64][nxy] tiled transpose, streaming out-writes
    bev_unpack_kernel<<<BV * NTILE, 256>>>(out);

    // 3) restore the zero-invariant via TMA bulk stores (1250 x 32KB)
    rezero_kernel<<<NCHUNK, 256>>>();
}